// round 14
// baseline (speedup 1.0000x reference)
#include <cuda_runtime.h>
#include <cstdint>
#include <math.h>

// ---------------- problem constants ----------------
#define NBS   2
#define NR    512
#define NROI  (NBS*NR)          // 1024
#define CH    256
#define OUTS  7
#define NPIX  (OUTS*OUTS)       // 49
#define FDIM  (CH*NPIX)         // 12544
#define DDIM  1024
#define NCLS  81
#define NREG  320
#define NHEAD (NCLS + NREG)     // 401
#define NHPAD 512               // padded head cols (4 x 128)
#define KS1   4                 // split-K for fc1
#define KS2   4                 // split-K for fc2
#define KSH   8                 // split-K for heads (grid 4x8x8 = 256 CTAs)

// ---------------- device scratch ----------------
__device__ float g_X[(size_t)NROI * FDIM];      // pooled features (tf32-rounded)
__device__ float g_Y[(size_t)NROI * DDIM];      // fc1 out (tf32-rounded)
__device__ float g_Z[(size_t)NROI * DDIM];      // fc2 out (tf32-rounded)
__device__ float g_W1r[(size_t)DDIM * FDIM];    // tf32 W1
__device__ float g_W2r[(size_t)DDIM * DDIM];    // tf32 W2
__device__ float g_WHr[(size_t)NHPAD * DDIM];   // tf32 [Wc;Wr;0-pad] (zero-init)
__device__ float g_P[(size_t)KSH * NROI * DDIM]; // split-K partials (32MB)
__device__ int   g_lvl[NROI];
__device__ float g_meta[NROI * 4];

// ---------------- helpers ----------------
__device__ __forceinline__ float tf32_rna(float x) {
    uint32_t r; asm("cvt.rna.tf32.f32 %0, %1;" : "=r"(r) : "f"(x));
    return __uint_as_float(r);
}
__device__ __forceinline__ uint32_t smem_u32(const void* p) {
    uint32_t a;
    asm("{ .reg .u64 t; cvta.to.shared.u64 t, %1; cvt.u32.u64 %0, t; }" : "=r"(a) : "l"(p));
    return a;
}
#define CP16(dst, src) \
    asm volatile("cp.async.cg.shared.global [%0], [%1], 16;" :: "r"(dst), "l"(src) : "memory")
#define CPCOMMIT() asm volatile("cp.async.commit_group;" ::: "memory")
#define CPWAIT3()  asm volatile("cp.async.wait_group 3;" ::: "memory")

__device__ __forceinline__ void mma_tf32(float c[4], const uint32_t a[4], const uint32_t b[2]) {
    asm volatile(
        "mma.sync.aligned.m16n8k8.row.col.f32.tf32.tf32.f32 "
        "{%0,%1,%2,%3}, {%4,%5,%6,%7}, {%8,%9}, {%0,%1,%2,%3};"
        : "+f"(c[0]), "+f"(c[1]), "+f"(c[2]), "+f"(c[3])
        : "r"(a[0]), "r"(a[1]), "r"(a[2]), "r"(a[3]), "r"(b[0]), "r"(b[1]));
}

// ---------------- roi prep ----------------
__global__ void roi_prep_kernel(const float* __restrict__ rois) {
    int i = blockIdx.x * blockDim.x + threadIdx.x;
    if (i >= NROI) return;
    float x1 = rois[i * 4 + 0], y1 = rois[i * 4 + 1];
    float x2 = rois[i * 4 + 2], y2 = rois[i * 4 + 3];
    float w = x2 - x1, h = y2 - y1;
    float lv = floorf(4.0f + log2f(sqrtf(w * h) / 224.0f + 1e-6f));
    int li = (int)lv - 2;
    g_lvl[i] = li;
    int lic = li < 0 ? 0 : (li > 3 ? 3 : li);
    float scale = 1.0f / (float)(4 << lic);
    float x1s = x1 * scale, y1s = y1 * scale;
    float rw = fmaxf(x2 * scale - x1s, 1.0f);
    float rh = fmaxf(y2 * scale - y1s, 1.0f);
    g_meta[i * 4 + 0] = x1s;
    g_meta[i * 4 + 1] = y1s;
    g_meta[i * 4 + 2] = rw / (float)OUTS;
    g_meta[i * 4 + 3] = rh / (float)OUTS;
}

// ---------------- fused roi_align + weight-round, block-interleaved ----------
// align: 8 channels/thread, branch-free gathers (latency-bound)
// round: W1/W2/heads tf32 rounding (DRAM-bound) — interleaved per 16-block period
#define ABLKS 6272     // align blocks: NROI*(CH/8)*NPIX / 256 (exact)
#define N4W1 (DDIM * FDIM / 4)
#define N4W2 (DDIM * DDIM / 4)
#define N4WH (NHEAD * DDIM / 4)
#define RBLKS 13969    // round blocks: (N4W1+N4W2+N4WH) / 256 (exact)
#define FUSED_GRID ((RBLKS / 10 + 1) * 16)   // 22352

__device__ __forceinline__ void do_align(int idx,
                                         const float* __restrict__ f2,
                                         const float* __restrict__ f3,
                                         const float* __restrict__ f4,
                                         const float* __restrict__ f5) {
    int n   = idx / ((CH / 8) * NPIX);
    int rem = idx - n * ((CH / 8) * NPIX);
    int c8  = rem / NPIX;
    int p   = rem - c8 * NPIX;
    int c0  = c8 * 8;

    size_t obase = (size_t)n * FDIM + (size_t)c0 * NPIX + p;

    int li = g_lvl[n];
    if (li < 0 || li > 3) {
        #pragma unroll
        for (int c = 0; c < 8; c++) g_X[obase + (size_t)c * NPIX] = 0.0f;
        return;
    }

    int ph = p / OUTS, pw = p - ph * OUTS;
    const float* f; int H;
    if      (li == 0) { f = f2; H = 200; }
    else if (li == 1) { f = f3; H = 100; }
    else if (li == 2) { f = f4; H = 50;  }
    else              { f = f5; H = 25;  }
    int W = H;
    int HW = H * W;
    int b = (n >= NR) ? 1 : 0;
    const float* base = f + ((size_t)b * CH + c0) * (size_t)HW;

    float x1 = g_meta[n * 4 + 0], y1 = g_meta[n * 4 + 1];
    float bw = g_meta[n * 4 + 2], bh = g_meta[n * 4 + 3];

    int yo0[2], yo1[2]; float lys[2]; float vyf[2];
    int xo0[2], xo1[2]; float lxs[2]; float vxf[2];
    #pragma unroll
    for (int i = 0; i < 2; i++) {
        float y = y1 + ((float)ph + 0.25f + 0.5f * (float)i) * bh;
        vyf[i] = ((y > -1.0f) && (y < (float)H)) ? 1.0f : 0.0f;
        float yc = fminf(fmaxf(y, 0.0f), (float)(H - 1));
        float y0f = floorf(yc);
        int y0 = (int)y0f;
        yo0[i] = y0 * W;
        yo1[i] = min(y0 + 1, H - 1) * W;
        lys[i] = yc - y0f;

        float x = x1 + ((float)pw + 0.25f + 0.5f * (float)i) * bw;
        vxf[i] = ((x > -1.0f) && (x < (float)W)) ? 1.0f : 0.0f;
        float xc = fminf(fmaxf(x, 0.0f), (float)(W - 1));
        float x0f = floorf(xc);
        xo0[i] = (int)x0f;
        xo1[i] = min((int)x0f + 1, W - 1);
        lxs[i] = xc - x0f;
    }

    int   off[16];
    float wgt[16];
    #pragma unroll
    for (int iy = 0; iy < 2; iy++) {
        #pragma unroll
        for (int ix = 0; ix < 2; ix++) {
            float v = vyf[iy] * vxf[ix];
            float ly = lys[iy], lx = lxs[ix];
            int s = (iy * 2 + ix) * 4;
            off[s + 0] = yo0[iy] + xo0[ix]; wgt[s + 0] = v * (1.0f - ly) * (1.0f - lx);
            off[s + 1] = yo0[iy] + xo1[ix]; wgt[s + 1] = v * (1.0f - ly) * lx;
            off[s + 2] = yo1[iy] + xo0[ix]; wgt[s + 2] = v * ly * (1.0f - lx);
            off[s + 3] = yo1[iy] + xo1[ix]; wgt[s + 3] = v * ly * lx;
        }
    }

    #pragma unroll
    for (int c = 0; c < 8; c++) {
        const float* bc = base + (size_t)c * HW;
        float v[16];
        #pragma unroll
        for (int q = 0; q < 16; q++) v[q] = bc[off[q]];
        float acc = 0.0f;
        #pragma unroll
        for (int q = 0; q < 16; q++) acc = fmaf(wgt[q], v[q], acc);
        g_X[obase + (size_t)c * NPIX] = tf32_rna(acc * 0.25f);
    }
}

__device__ __forceinline__ void do_round(int i,
                                         const float4* __restrict__ w1,
                                         const float4* __restrict__ w2,
                                         const float4* __restrict__ wc,
                                         const float4* __restrict__ wr) {
    const float4* in; int j;
    if (i < N4W1) { in = w1; j = i; }
    else if (i < N4W1 + N4W2) { in = w2; j = i - N4W1; }
    else {
        j = i - N4W1 - N4W2;
        int row = (j * 4) / DDIM;
        if (row < NCLS) { in = wc; }
        else            { in = wr; j -= NCLS * DDIM / 4; }
    }
    float4 v = in[j];
    v.x = tf32_rna(v.x); v.y = tf32_rna(v.y);
    v.z = tf32_rna(v.z); v.w = tf32_rna(v.w);
    if (i < N4W1)              ((float4*)g_W1r)[i] = v;
    else if (i < N4W1 + N4W2)  ((float4*)g_W2r)[i - N4W1] = v;
    else                       ((float4*)g_WHr)[i - N4W1 - N4W2] = v; // rows 401..511 stay 0
}

__global__ void __launch_bounds__(256)
align_round_kernel(const float* __restrict__ f2, const float* __restrict__ f3,
                   const float* __restrict__ f4, const float* __restrict__ f5,
                   const float4* __restrict__ w1, const float4* __restrict__ w2,
                   const float4* __restrict__ wc, const float4* __restrict__ wr) {
    int pidx = blockIdx.x >> 4;
    int slot = blockIdx.x & 15;
    if (slot < 6) {
        int ablk = pidx * 6 + slot;
        if (ablk >= ABLKS) return;
        do_align(ablk * 256 + threadIdx.x, f2, f3, f4, f5);
    } else {
        int rblk = pidx * 10 + (slot - 6);
        if (rblk >= RBLKS) return;
        do_round(rblk * 256 + threadIdx.x, w1, w2, wc, wr);
    }
}

// ---------------- mma.sync tf32 GEMM, tile 128x128, split-K (R11 config) -----
// P[z][M, (ld=DDIM)] = A[M,Kz]*B[N,Kz]^T ; BK=16, 5-stage cp.async, 2 CTAs/SM,
// 8 warps (4M x 2N), warp tile 32x64 (2 m-atoms x 8 n-atoms).
#define PADK   20
#define ASZ    (128 * PADK)
#define BSZ    (128 * PADK)
#define NSTG   5
#define GSMEM  ((NSTG * (ASZ + BSZ)) * 4)   // 102400 bytes

__global__ void __launch_bounds__(256, 2)
gemm_mma_tf32(const float* __restrict__ A, const float* __restrict__ B,
              float* __restrict__ P, int K, int kc) {
    extern __shared__ float sm[];
    float* smA = sm;
    float* smB = sm + NSTG * ASZ;
    uint32_t sA = smem_u32(smA);
    uint32_t sB = smem_u32(smB);

    const int tid = threadIdx.x;
    const int wid = tid >> 5, lane = tid & 31;
    const int grp = lane >> 2, tig = lane & 3;
    const int wm = (wid & 3) * 32;       // warp M offset
    const int wn = (wid >> 2) * 64;      // warp N offset

    const int rowA0 = blockIdx.y * 128;
    const int colB0 = blockIdx.x * 128;
    const int kbase = blockIdx.z * kc * 16;
    const int nk = kc;

    const int grow = tid >> 1, gc = (tid & 1) * 8;
    const float* gA = A + (size_t)(rowA0 + grow) * K + kbase + gc;
    const float* gB = B + (size_t)(colB0 + grow) * K + kbase + gc;
    const uint32_t dA0 = sA + (uint32_t)(grow * PADK + gc) * 4;
    const uint32_t dA1 = dA0 + 16;
    const uint32_t dB0 = sB + (uint32_t)(grow * PADK + gc) * 4;
    const uint32_t dB1 = dB0 + 16;

    float c[2][8][4];
    #pragma unroll
    for (int i = 0; i < 2; i++)
        #pragma unroll
        for (int j = 0; j < 8; j++)
            #pragma unroll
            for (int q = 0; q < 4; q++) c[i][j][q] = 0.0f;

    #pragma unroll
    for (int s = 0; s < NSTG - 1; s++) {
        if (s < nk) {
            CP16(dA0 + (uint32_t)(s * ASZ * 4), gA + (size_t)s * 16);
            CP16(dA1 + (uint32_t)(s * ASZ * 4), gA + (size_t)s * 16 + 4);
            CP16(dB0 + (uint32_t)(s * BSZ * 4), gB + (size_t)s * 16);
            CP16(dB1 + (uint32_t)(s * BSZ * 4), gB + (size_t)s * 16 + 4);
        }
        CPCOMMIT();
    }

    int stage = 0;
    for (int kt = 0; kt < nk; kt++) {
        CPWAIT3();            // chunks 0..kt complete
        __syncthreads();      // readers of stage being overwritten are done

        int pk = kt + NSTG - 1;
        int ps = stage + (NSTG - 1); if (ps >= NSTG) ps -= NSTG;
        if (pk < nk) {
            CP16(dA0 + (uint32_t)(ps * ASZ * 4), gA + (size_t)pk * 16);
            CP16(dA1 + (uint32_t)(ps * ASZ * 4), gA + (size_t)pk * 16 + 4);
            CP16(dB0 + (uint32_t)(ps * BSZ * 4), gB + (size_t)pk * 16);
            CP16(dB1 + (uint32_t)(ps * BSZ * 4), gB + (size_t)pk * 16 + 4);
        }
        CPCOMMIT();

        const float* As_ = smA + stage * ASZ;
        const float* Bs_ = smB + stage * BSZ;

        #pragma unroll
        for (int ka = 0; ka < 2; ka++) {
            int k0 = ka * 8;
            uint32_t a[2][4], b[8][2];
            #pragma unroll
            for (int ma = 0; ma < 2; ma++) {
                int base = (wm + ma * 16 + grp) * PADK + k0 + tig;
                a[ma][0] = __float_as_uint(As_[base]);
                a[ma][1] = __float_as_uint(As_[base + 8 * PADK]);
                a[ma][2] = __float_as_uint(As_[base + 4]);
                a[ma][3] = __float_as_uint(As_[base + 8 * PADK + 4]);
            }
            #pragma unroll
            for (int na = 0; na < 8; na++) {
                int base = (wn + na * 8 + grp) * PADK + k0 + tig;
                b[na][0] = __float_as_uint(Bs_[base]);
                b[na][1] = __float_as_uint(Bs_[base + 4]);
            }
            #pragma unroll
            for (int ma = 0; ma < 2; ma++)
                #pragma unroll
                for (int na = 0; na < 8; na++)
                    mma_tf32(c[ma][na], a[ma], b[na]);
        }

        if (++stage == NSTG) stage = 0;
    }

    float* Pp = P + (size_t)blockIdx.z * NROI * DDIM;
    #pragma unroll
    for (int ma = 0; ma < 2; ma++) {
        int r0 = rowA0 + wm + ma * 16 + grp;
        #pragma unroll
        for (int na = 0; na < 8; na++) {
            int col = colB0 + wn + na * 8 + tig * 2;
            *(float2*)&Pp[(size_t)r0 * DDIM + col]       = make_float2(c[ma][na][0], c[ma][na][1]);
            *(float2*)&Pp[(size_t)(r0 + 8) * DDIM + col] = make_float2(c[ma][na][2], c[ma][na][3]);
        }
    }
}

// ---------------- split-K reduce + bias + relu (+ tf32 round) ----------------
template<int NP, int RND>
__global__ void __launch_bounds__(256)
reduce_kernel(const float* __restrict__ bias, float* __restrict__ C) {
    int i = blockIdx.x * blockDim.x + threadIdx.x;   // float4 index
    if (i >= NROI * DDIM / 4) return;
    const float4* P = (const float4*)g_P;
    const size_t stride = (size_t)NROI * DDIM / 4;
    float4 v = P[i];
    #pragma unroll
    for (int p = 1; p < NP; p++) {
        float4 u = P[i + p * stride];
        v.x += u.x; v.y += u.y; v.z += u.z; v.w += u.w;
    }
    int col = (i * 4) & (DDIM - 1);
    float4 bv = *(const float4*)&bias[col];
    float4 r;
    r.x = fmaxf(v.x + bv.x, 0.0f);
    r.y = fmaxf(v.y + bv.y, 0.0f);
    r.z = fmaxf(v.z + bv.z, 0.0f);
    r.w = fmaxf(v.w + bv.w, 0.0f);
    if (RND) { r.x = tf32_rna(r.x); r.y = tf32_rna(r.y);
               r.z = tf32_rna(r.z); r.w = tf32_rna(r.w); }
    ((float4*)C)[i] = r;
}

// ---------------- heads reduce: bias + scatter into cls/reg layout ----------
__global__ void __launch_bounds__(256)
reduce_heads_kernel(const float* __restrict__ bc, const float* __restrict__ br,
                    float* __restrict__ out) {
    int i = blockIdx.x * blockDim.x + threadIdx.x;
    if (i >= NROI * NHEAD) return;
    int m = i / NHEAD;
    int col = i - m * NHEAD;
    const float* P = g_P;
    const size_t stride = (size_t)NROI * DDIM;
    size_t o = (size_t)m * DDIM + col;
    float v = P[o];
    #pragma unroll
    for (int p = 1; p < KSH; p++) v += P[o + p * stride];
    if (col < NCLS)
        out[(size_t)m * NCLS + col] = v + bc[col];
    else
        out[(size_t)NROI * NCLS + (size_t)m * NREG + (col - NCLS)] = v + br[col - NCLS];
}

// ---------------- launch ----------------
extern "C" void kernel_launch(void* const* d_in, const int* in_sizes, int n_in,
                              void* d_out, int out_size) {
    const float* f2   = (const float*)d_in[0];
    const float* f3   = (const float*)d_in[1];
    const float* f4   = (const float*)d_in[2];
    const float* f5   = (const float*)d_in[3];
    const float* rois = (const float*)d_in[4];
    const float* W1   = (const float*)d_in[5];
    const float* b1   = (const float*)d_in[6];
    const float* W2   = (const float*)d_in[7];
    const float* b2   = (const float*)d_in[8];
    const float* Wc   = (const float*)d_in[9];
    const float* bc   = (const float*)d_in[10];
    const float* Wr   = (const float*)d_in[11];
    const float* br   = (const float*)d_in[12];
    float* out = (float*)d_out;

    float *X, *Y, *Z, *W1r, *W2r, *WHr, *Pb;
    cudaGetSymbolAddress((void**)&X, g_X);
    cudaGetSymbolAddress((void**)&Y, g_Y);
    cudaGetSymbolAddress((void**)&Z, g_Z);
    cudaGetSymbolAddress((void**)&W1r, g_W1r);
    cudaGetSymbolAddress((void**)&W2r, g_W2r);
    cudaGetSymbolAddress((void**)&WHr, g_WHr);
    cudaGetSymbolAddress((void**)&Pb, g_P);

    cudaFuncSetAttribute(gemm_mma_tf32, cudaFuncAttributeMaxDynamicSharedMemorySize, GSMEM);

    roi_prep_kernel<<<(NROI + 255) / 256, 256>>>(rois);

    // fused align + weight-round, block-interleaved for DRAM/latency overlap
    align_round_kernel<<<FUSED_GRID, 256>>>(f2, f3, f4, f5,
        (const float4*)W1, (const float4*)W2, (const float4*)Wc, (const float4*)Wr);

    int nred = NROI * DDIM / 4;
    // fc1: K=12544, 784 BK-iters, 196 per split (grid 8x8x4 = 256 CTAs, 1 wave)
    gemm_mma_tf32<<<dim3(DDIM / 128, NROI / 128, KS1), 256, GSMEM>>>(X, W1r, Pb, FDIM, 196);
    reduce_kernel<KS1, 1><<<(nred + 255) / 256, 256>>>(b1, Y);
    // fc2: K=1024, 64 BK-iters, 16 per split (grid 8x8x4)
    gemm_mma_tf32<<<dim3(DDIM / 128, NROI / 128, KS2), 256, GSMEM>>>(Y, W2r, Pb, DDIM, 16);
    reduce_kernel<KS2, 1><<<(nred + 255) / 256, 256>>>(b2, Z);
    // heads: M=1024, N=512(pad), K=1024, 8 per split (grid 4x8x8 = 256 CTAs)
    gemm_mma_tf32<<<dim3(NHPAD / 128, NROI / 128, KSH), 256, GSMEM>>>(Z, WHr, Pb, DDIM, 8);
    reduce_heads_kernel<<<(NROI * NHEAD + 255) / 256, 256>>>(bc, br, out);
}

// round 15
// speedup vs baseline: 1.0142x; 1.0142x over previous
#include <cuda_runtime.h>
#include <cstdint>
#include <math.h>

// ---------------- problem constants ----------------
#define NBS   2
#define NR    512
#define NROI  (NBS*NR)          // 1024
#define CH    256
#define OUTS  7
#define NPIX  (OUTS*OUTS)       // 49
#define FDIM  (CH*NPIX)         // 12544
#define DDIM  1024
#define NCLS  81
#define NREG  320
#define NHEAD (NCLS + NREG)     // 401
#define NHPAD 512               // padded head cols (4 x 128)
#define KS1   4                 // split-K for fc1
#define KS2   4                 // split-K for fc2
#define KSH   8                 // split-K for heads (grid 4x8x8 = 256 CTAs)

// ---------------- device scratch ----------------
__device__ float g_X[(size_t)NROI * FDIM];      // pooled features (tf32-rounded)
__device__ float g_Y[(size_t)NROI * DDIM];      // fc1 out (tf32-rounded)
__device__ float g_Z[(size_t)NROI * DDIM];      // fc2 out (tf32-rounded)
__device__ float g_WH[(size_t)NHPAD * DDIM];    // [Wc;Wr;0-pad] raw copy (zero-init)
__device__ float g_P[(size_t)KSH * NROI * DDIM]; // split-K partials (32MB)
__device__ int   g_lvl[NROI];
__device__ float g_meta[NROI * 4];

// ---------------- helpers ----------------
__device__ __forceinline__ float tf32_rna(float x) {
    uint32_t r; asm("cvt.rna.tf32.f32 %0, %1;" : "=r"(r) : "f"(x));
    return __uint_as_float(r);
}
__device__ __forceinline__ uint32_t tf32_rna_u(float x) {
    uint32_t r; asm("cvt.rna.tf32.f32 %0, %1;" : "=r"(r) : "f"(x));
    return r;
}
__device__ __forceinline__ uint32_t smem_u32(const void* p) {
    uint32_t a;
    asm("{ .reg .u64 t; cvta.to.shared.u64 t, %1; cvt.u32.u64 %0, t; }" : "=r"(a) : "l"(p));
    return a;
}
#define CP16(dst, src) \
    asm volatile("cp.async.cg.shared.global [%0], [%1], 16;" :: "r"(dst), "l"(src) : "memory")
#define CPCOMMIT() asm volatile("cp.async.commit_group;" ::: "memory")
#define CPWAIT3()  asm volatile("cp.async.wait_group 3;" ::: "memory")

__device__ __forceinline__ void mma_tf32(float c[4], const uint32_t a[4], const uint32_t b[2]) {
    asm volatile(
        "mma.sync.aligned.m16n8k8.row.col.f32.tf32.tf32.f32 "
        "{%0,%1,%2,%3}, {%4,%5,%6,%7}, {%8,%9}, {%0,%1,%2,%3};"
        : "+f"(c[0]), "+f"(c[1]), "+f"(c[2]), "+f"(c[3])
        : "r"(a[0]), "r"(a[1]), "r"(a[2]), "r"(a[3]), "r"(b[0]), "r"(b[1]));
}

// ---------------- roi prep ----------------
__global__ void roi_prep_kernel(const float* __restrict__ rois) {
    int i = blockIdx.x * blockDim.x + threadIdx.x;
    if (i >= NROI) return;
    float x1 = rois[i * 4 + 0], y1 = rois[i * 4 + 1];
    float x2 = rois[i * 4 + 2], y2 = rois[i * 4 + 3];
    float w = x2 - x1, h = y2 - y1;
    float lv = floorf(4.0f + log2f(sqrtf(w * h) / 224.0f + 1e-6f));
    int li = (int)lv - 2;
    g_lvl[i] = li;
    int lic = li < 0 ? 0 : (li > 3 ? 3 : li);
    float scale = 1.0f / (float)(4 << lic);
    float x1s = x1 * scale, y1s = y1 * scale;
    float rw = fmaxf(x2 * scale - x1s, 1.0f);
    float rh = fmaxf(y2 * scale - y1s, 1.0f);
    g_meta[i * 4 + 0] = x1s;
    g_meta[i * 4 + 1] = y1s;
    g_meta[i * 4 + 2] = rw / (float)OUTS;
    g_meta[i * 4 + 3] = rh / (float)OUTS;
}

// ---------------- roi align: 8 channels/thread, branch-free gathers ----------
__global__ void __launch_bounds__(256)
roi_align_kernel(const float* __restrict__ f2, const float* __restrict__ f3,
                 const float* __restrict__ f4, const float* __restrict__ f5) {
    int idx = blockIdx.x * blockDim.x + threadIdx.x;
    if (idx >= NROI * (CH / 8) * NPIX) return;
    int n   = idx / ((CH / 8) * NPIX);
    int rem = idx - n * ((CH / 8) * NPIX);
    int c8  = rem / NPIX;
    int p   = rem - c8 * NPIX;
    int c0  = c8 * 8;

    size_t obase = (size_t)n * FDIM + (size_t)c0 * NPIX + p;

    int li = g_lvl[n];
    if (li < 0 || li > 3) {
        #pragma unroll
        for (int c = 0; c < 8; c++) g_X[obase + (size_t)c * NPIX] = 0.0f;
        return;
    }

    int ph = p / OUTS, pw = p - ph * OUTS;
    const float* f; int H;
    if      (li == 0) { f = f2; H = 200; }
    else if (li == 1) { f = f3; H = 100; }
    else if (li == 2) { f = f4; H = 50;  }
    else              { f = f5; H = 25;  }
    int W = H;
    int HW = H * W;
    int b = (n >= NR) ? 1 : 0;
    const float* base = f + ((size_t)b * CH + c0) * (size_t)HW;

    float x1 = g_meta[n * 4 + 0], y1 = g_meta[n * 4 + 1];
    float bw = g_meta[n * 4 + 2], bh = g_meta[n * 4 + 3];

    int yo0[2], yo1[2]; float lys[2]; float vyf[2];
    int xo0[2], xo1[2]; float lxs[2]; float vxf[2];
    #pragma unroll
    for (int i = 0; i < 2; i++) {
        float y = y1 + ((float)ph + 0.25f + 0.5f * (float)i) * bh;
        vyf[i] = ((y > -1.0f) && (y < (float)H)) ? 1.0f : 0.0f;
        float yc = fminf(fmaxf(y, 0.0f), (float)(H - 1));
        float y0f = floorf(yc);
        int y0 = (int)y0f;
        yo0[i] = y0 * W;
        yo1[i] = min(y0 + 1, H - 1) * W;
        lys[i] = yc - y0f;

        float x = x1 + ((float)pw + 0.25f + 0.5f * (float)i) * bw;
        vxf[i] = ((x > -1.0f) && (x < (float)W)) ? 1.0f : 0.0f;
        float xc = fminf(fmaxf(x, 0.0f), (float)(W - 1));
        float x0f = floorf(xc);
        xo0[i] = (int)x0f;
        xo1[i] = min((int)x0f + 1, W - 1);
        lxs[i] = xc - x0f;
    }

    int   off[16];
    float wgt[16];
    #pragma unroll
    for (int iy = 0; iy < 2; iy++) {
        #pragma unroll
        for (int ix = 0; ix < 2; ix++) {
            float v = vyf[iy] * vxf[ix];
            float ly = lys[iy], lx = lxs[ix];
            int s = (iy * 2 + ix) * 4;
            off[s + 0] = yo0[iy] + xo0[ix]; wgt[s + 0] = v * (1.0f - ly) * (1.0f - lx);
            off[s + 1] = yo0[iy] + xo1[ix]; wgt[s + 1] = v * (1.0f - ly) * lx;
            off[s + 2] = yo1[iy] + xo0[ix]; wgt[s + 2] = v * ly * (1.0f - lx);
            off[s + 3] = yo1[iy] + xo1[ix]; wgt[s + 3] = v * ly * lx;
        }
    }

    #pragma unroll
    for (int c = 0; c < 8; c++) {
        const float* bc = base + (size_t)c * HW;
        float v[16];
        #pragma unroll
        for (int q = 0; q < 16; q++) v[q] = bc[off[q]];
        float acc = 0.0f;
        #pragma unroll
        for (int q = 0; q < 16; q++) acc = fmaf(wgt[q], v[q], acc);
        g_X[obase + (size_t)c * NPIX] = tf32_rna(acc * 0.25f);
    }
}

// ---------------- heads weight concat: [Wc;Wr] -> g_WH (raw copy) -----------
#define N4WH (NHEAD * DDIM / 4)
__global__ void concat_wh_kernel(const float4* __restrict__ wc,
                                 const float4* __restrict__ wr) {
    int i = blockIdx.x * blockDim.x + threadIdx.x;
    if (i >= N4WH) return;
    int row = (i * 4) / DDIM;
    float4 v = (row < NCLS) ? wc[i] : wr[i - NCLS * DDIM / 4];
    ((float4*)g_WH)[i] = v;   // rows 401..511 stay zero (static init)
}

// ---------------- mma.sync tf32 GEMM, tile 128x128, split-K ----------------
// B-fragments rounded to tf32 (rna) in-register after LDS — numerically
// identical to pre-rounding W, but removes the weight-round pass entirely.
// P[z][M, (ld=DDIM)] = A[M,Kz]*round(B[N,Kz])^T ; BK=16, 5-stage cp.async,
// 2 CTAs/SM, 8 warps (4M x 2N), warp tile 32x64.
#define PADK   20
#define ASZ    (128 * PADK)
#define BSZ    (128 * PADK)
#define NSTG   5
#define GSMEM  ((NSTG * (ASZ + BSZ)) * 4)   // 102400 bytes

__global__ void __launch_bounds__(256, 2)
gemm_mma_tf32(const float* __restrict__ A, const float* __restrict__ B,
              float* __restrict__ P, int K, int kc) {
    extern __shared__ float sm[];
    float* smA = sm;
    float* smB = sm + NSTG * ASZ;
    uint32_t sA = smem_u32(smA);
    uint32_t sB = smem_u32(smB);

    const int tid = threadIdx.x;
    const int wid = tid >> 5, lane = tid & 31;
    const int grp = lane >> 2, tig = lane & 3;
    const int wm = (wid & 3) * 32;       // warp M offset
    const int wn = (wid >> 2) * 64;      // warp N offset

    const int rowA0 = blockIdx.y * 128;
    const int colB0 = blockIdx.x * 128;
    const int kbase = blockIdx.z * kc * 16;
    const int nk = kc;

    const int grow = tid >> 1, gc = (tid & 1) * 8;
    const float* gA = A + (size_t)(rowA0 + grow) * K + kbase + gc;
    const float* gB = B + (size_t)(colB0 + grow) * K + kbase + gc;
    const uint32_t dA0 = sA + (uint32_t)(grow * PADK + gc) * 4;
    const uint32_t dA1 = dA0 + 16;
    const uint32_t dB0 = sB + (uint32_t)(grow * PADK + gc) * 4;
    const uint32_t dB1 = dB0 + 16;

    float c[2][8][4];
    #pragma unroll
    for (int i = 0; i < 2; i++)
        #pragma unroll
        for (int j = 0; j < 8; j++)
            #pragma unroll
            for (int q = 0; q < 4; q++) c[i][j][q] = 0.0f;

    #pragma unroll
    for (int s = 0; s < NSTG - 1; s++) {
        if (s < nk) {
            CP16(dA0 + (uint32_t)(s * ASZ * 4), gA + (size_t)s * 16);
            CP16(dA1 + (uint32_t)(s * ASZ * 4), gA + (size_t)s * 16 + 4);
            CP16(dB0 + (uint32_t)(s * BSZ * 4), gB + (size_t)s * 16);
            CP16(dB1 + (uint32_t)(s * BSZ * 4), gB + (size_t)s * 16 + 4);
        }
        CPCOMMIT();
    }

    int stage = 0;
    for (int kt = 0; kt < nk; kt++) {
        CPWAIT3();            // chunks 0..kt complete
        __syncthreads();      // readers of stage being overwritten are done

        int pk = kt + NSTG - 1;
        int ps = stage + (NSTG - 1); if (ps >= NSTG) ps -= NSTG;
        if (pk < nk) {
            CP16(dA0 + (uint32_t)(ps * ASZ * 4), gA + (size_t)pk * 16);
            CP16(dA1 + (uint32_t)(ps * ASZ * 4), gA + (size_t)pk * 16 + 4);
            CP16(dB0 + (uint32_t)(ps * BSZ * 4), gB + (size_t)pk * 16);
            CP16(dB1 + (uint32_t)(ps * BSZ * 4), gB + (size_t)pk * 16 + 4);
        }
        CPCOMMIT();

        const float* As_ = smA + stage * ASZ;
        const float* Bs_ = smB + stage * BSZ;

        #pragma unroll
        for (int ka = 0; ka < 2; ka++) {
            int k0 = ka * 8;
            uint32_t a[2][4], b[8][2];
            #pragma unroll
            for (int ma = 0; ma < 2; ma++) {
                int base = (wm + ma * 16 + grp) * PADK + k0 + tig;
                a[ma][0] = __float_as_uint(As_[base]);
                a[ma][1] = __float_as_uint(As_[base + 8 * PADK]);
                a[ma][2] = __float_as_uint(As_[base + 4]);
                a[ma][3] = __float_as_uint(As_[base + 8 * PADK + 4]);
            }
            #pragma unroll
            for (int na = 0; na < 8; na++) {
                int base = (wn + na * 8 + grp) * PADK + k0 + tig;
                b[na][0] = tf32_rna_u(Bs_[base]);
                b[na][1] = tf32_rna_u(Bs_[base + 4]);
            }
            #pragma unroll
            for (int ma = 0; ma < 2; ma++)
                #pragma unroll
                for (int na = 0; na < 8; na++)
                    mma_tf32(c[ma][na], a[ma], b[na]);
        }

        if (++stage == NSTG) stage = 0;
    }

    float* Pp = P + (size_t)blockIdx.z * NROI * DDIM;
    #pragma unroll
    for (int ma = 0; ma < 2; ma++) {
        int r0 = rowA0 + wm + ma * 16 + grp;
        #pragma unroll
        for (int na = 0; na < 8; na++) {
            int col = colB0 + wn + na * 8 + tig * 2;
            *(float2*)&Pp[(size_t)r0 * DDIM + col]       = make_float2(c[ma][na][0], c[ma][na][1]);
            *(float2*)&Pp[(size_t)(r0 + 8) * DDIM + col] = make_float2(c[ma][na][2], c[ma][na][3]);
        }
    }
}

// ---------------- split-K reduce + bias + relu (+ tf32 round) ----------------
template<int NP, int RND>
__global__ void __launch_bounds__(256)
reduce_kernel(const float* __restrict__ bias, float* __restrict__ C) {
    int i = blockIdx.x * blockDim.x + threadIdx.x;   // float4 index
    if (i >= NROI * DDIM / 4) return;
    const float4* P = (const float4*)g_P;
    const size_t stride = (size_t)NROI * DDIM / 4;
    float4 v = P[i];
    #pragma unroll
    for (int p = 1; p < NP; p++) {
        float4 u = P[i + p * stride];
        v.x += u.x; v.y += u.y; v.z += u.z; v.w += u.w;
    }
    int col = (i * 4) & (DDIM - 1);
    float4 bv = *(const float4*)&bias[col];
    float4 r;
    r.x = fmaxf(v.x + bv.x, 0.0f);
    r.y = fmaxf(v.y + bv.y, 0.0f);
    r.z = fmaxf(v.z + bv.z, 0.0f);
    r.w = fmaxf(v.w + bv.w, 0.0f);
    if (RND) { r.x = tf32_rna(r.x); r.y = tf32_rna(r.y);
               r.z = tf32_rna(r.z); r.w = tf32_rna(r.w); }
    ((float4*)C)[i] = r;
}

// ---------------- heads reduce: bias + scatter into cls/reg layout ----------
__global__ void __launch_bounds__(256)
reduce_heads_kernel(const float* __restrict__ bc, const float* __restrict__ br,
                    float* __restrict__ out) {
    int i = blockIdx.x * blockDim.x + threadIdx.x;
    if (i >= NROI * NHEAD) return;
    int m = i / NHEAD;
    int col = i - m * NHEAD;
    const float* P = g_P;
    const size_t stride = (size_t)NROI * DDIM;
    size_t o = (size_t)m * DDIM + col;
    float v = P[o];
    #pragma unroll
    for (int p = 1; p < KSH; p++) v += P[o + p * stride];
    if (col < NCLS)
        out[(size_t)m * NCLS + col] = v + bc[col];
    else
        out[(size_t)NROI * NCLS + (size_t)m * NREG + (col - NCLS)] = v + br[col - NCLS];
}

// ---------------- launch ----------------
extern "C" void kernel_launch(void* const* d_in, const int* in_sizes, int n_in,
                              void* d_out, int out_size) {
    const float* f2   = (const float*)d_in[0];
    const float* f3   = (const float*)d_in[1];
    const float* f4   = (const float*)d_in[2];
    const float* f5   = (const float*)d_in[3];
    const float* rois = (const float*)d_in[4];
    const float* W1   = (const float*)d_in[5];
    const float* b1   = (const float*)d_in[6];
    const float* W2   = (const float*)d_in[7];
    const float* b2   = (const float*)d_in[8];
    const float* Wc   = (const float*)d_in[9];
    const float* bc   = (const float*)d_in[10];
    const float* Wr   = (const float*)d_in[11];
    const float* br   = (const float*)d_in[12];
    float* out = (float*)d_out;

    float *X, *Y, *Z, *WH, *Pb;
    cudaGetSymbolAddress((void**)&X, g_X);
    cudaGetSymbolAddress((void**)&Y, g_Y);
    cudaGetSymbolAddress((void**)&Z, g_Z);
    cudaGetSymbolAddress((void**)&WH, g_WH);
    cudaGetSymbolAddress((void**)&Pb, g_P);

    cudaFuncSetAttribute(gemm_mma_tf32, cudaFuncAttributeMaxDynamicSharedMemorySize, GSMEM);

    roi_prep_kernel<<<(NROI + 255) / 256, 256>>>(rois);

    int total = NROI * (CH / 8) * NPIX;
    roi_align_kernel<<<(total + 255) / 256, 256>>>(f2, f3, f4, f5);

    concat_wh_kernel<<<(N4WH + 255) / 256, 256>>>((const float4*)Wc, (const float4*)Wr);

    int nred = NROI * DDIM / 4;
    // fc1: K=12544, 784 BK-iters, 196 per split (grid 8x8x4 = 256 CTAs, 1 wave)
    gemm_mma_tf32<<<dim3(DDIM / 128, NROI / 128, KS1), 256, GSMEM>>>(X, W1, Pb, FDIM, 196);
    reduce_kernel<KS1, 1><<<(nred + 255) / 256, 256>>>(b1, Y);
    // fc2: K=1024, 64 BK-iters, 16 per split (grid 8x8x4)
    gemm_mma_tf32<<<dim3(DDIM / 128, NROI / 128, KS2), 256, GSMEM>>>(Y, W2, Pb, DDIM, 16);
    reduce_kernel<KS2, 1><<<(nred + 255) / 256, 256>>>(b2, Z);
    // heads: M=1024, N=512(pad), K=1024, 8 per split (grid 4x8x8 = 256 CTAs)
    gemm_mma_tf32<<<dim3(NHPAD / 128, NROI / 128, KSH), 256, GSMEM>>>(Z, WH, Pb, DDIM, 8);
    reduce_heads_kernel<<<(NROI * NHEAD + 255) / 256, 256>>>(bc, br, out);
}

// round 16
// speedup vs baseline: 1.1405x; 1.1245x over previous
#include <cuda_runtime.h>
#include <cstdint>
#include <math.h>

// ---------------- problem constants ----------------
#define NBS   2
#define NR    512
#define NROI  (NBS*NR)          // 1024
#define CH    256
#define OUTS  7
#define NPIX  (OUTS*OUTS)       // 49
#define FDIM  (CH*NPIX)         // 12544
#define DDIM  1024
#define NCLS  81
#define NREG  320
#define NHEAD (NCLS + NREG)     // 401
#define NHPAD 512               // padded head cols (4 x 128)
#define KS1   4                 // split-K for fc1
#define KS2   4                 // split-K for fc2
#define KSH   8                 // split-K for heads (grid 4x8x8 = 256 CTAs)

// ---------------- device scratch ----------------
__device__ float g_X[(size_t)NROI * FDIM];      // pooled features (tf32-rounded)
__device__ float g_Y[(size_t)NROI * DDIM];      // fc1 out (tf32-rounded)
__device__ float g_Z[(size_t)NROI * DDIM];      // fc2 out (tf32-rounded)
__device__ float g_WH[(size_t)NHPAD * DDIM];    // [Wc;Wr;0-pad] raw copy (zero-init)
__device__ float g_P[(size_t)KSH * NROI * DDIM]; // split-K partials (32MB)
__device__ int   g_lvl[NROI];
__device__ float g_meta[NROI * 4];

// ---------------- helpers ----------------
__device__ __forceinline__ float tf32_rna(float x) {
    uint32_t r; asm("cvt.rna.tf32.f32 %0, %1;" : "=r"(r) : "f"(x));
    return __uint_as_float(r);
}
__device__ __forceinline__ uint32_t tf32_rna_u(uint32_t x) {
    uint32_t r; asm("cvt.rna.tf32.f32 %0, %1;" : "=r"(r) : "f"(__uint_as_float(x)));
    return r;
}
__device__ __forceinline__ uint32_t smem_u32(const void* p) {
    uint32_t a;
    asm("{ .reg .u64 t; cvta.to.shared.u64 t, %1; cvt.u32.u64 %0, t; }" : "=r"(a) : "l"(p));
    return a;
}
#define CP16(dst, src) \
    asm volatile("cp.async.cg.shared.global [%0], [%1], 16;" :: "r"(dst), "l"(src) : "memory")
#define CPCOMMIT() asm volatile("cp.async.commit_group;" ::: "memory")
#define CPWAIT3()  asm volatile("cp.async.wait_group 3;" ::: "memory")
#define LDSM4(r0, r1, r2, r3, addr) \
    asm volatile("ldmatrix.sync.aligned.m8n8.x4.shared.b16 {%0,%1,%2,%3}, [%4];" \
        : "=r"(r0), "=r"(r1), "=r"(r2), "=r"(r3) : "r"(addr))

__device__ __forceinline__ void mma_tf32(float c[4], const uint32_t a[4], const uint32_t b[2]) {
    asm volatile(
        "mma.sync.aligned.m16n8k8.row.col.f32.tf32.tf32.f32 "
        "{%0,%1,%2,%3}, {%4,%5,%6,%7}, {%8,%9}, {%0,%1,%2,%3};"
        : "+f"(c[0]), "+f"(c[1]), "+f"(c[2]), "+f"(c[3])
        : "r"(a[0]), "r"(a[1]), "r"(a[2]), "r"(a[3]), "r"(b[0]), "r"(b[1]));
}

// ---------------- roi prep ----------------
__global__ void roi_prep_kernel(const float* __restrict__ rois) {
    int i = blockIdx.x * blockDim.x + threadIdx.x;
    if (i >= NROI) return;
    float x1 = rois[i * 4 + 0], y1 = rois[i * 4 + 1];
    float x2 = rois[i * 4 + 2], y2 = rois[i * 4 + 3];
    float w = x2 - x1, h = y2 - y1;
    float lv = floorf(4.0f + log2f(sqrtf(w * h) / 224.0f + 1e-6f));
    int li = (int)lv - 2;
    g_lvl[i] = li;
    int lic = li < 0 ? 0 : (li > 3 ? 3 : li);
    float scale = 1.0f / (float)(4 << lic);
    float x1s = x1 * scale, y1s = y1 * scale;
    float rw = fmaxf(x2 * scale - x1s, 1.0f);
    float rh = fmaxf(y2 * scale - y1s, 1.0f);
    g_meta[i * 4 + 0] = x1s;
    g_meta[i * 4 + 1] = y1s;
    g_meta[i * 4 + 2] = rw / (float)OUTS;
    g_meta[i * 4 + 3] = rh / (float)OUTS;
}

// ---------------- roi align: 8 channels/thread, branch-free gathers ----------
__global__ void __launch_bounds__(256)
roi_align_kernel(const float* __restrict__ f2, const float* __restrict__ f3,
                 const float* __restrict__ f4, const float* __restrict__ f5) {
    int idx = blockIdx.x * blockDim.x + threadIdx.x;
    if (idx >= NROI * (CH / 8) * NPIX) return;
    int n   = idx / ((CH / 8) * NPIX);
    int rem = idx - n * ((CH / 8) * NPIX);
    int c8  = rem / NPIX;
    int p   = rem - c8 * NPIX;
    int c0  = c8 * 8;

    size_t obase = (size_t)n * FDIM + (size_t)c0 * NPIX + p;

    int li = g_lvl[n];
    if (li < 0 || li > 3) {
        #pragma unroll
        for (int c = 0; c < 8; c++) g_X[obase + (size_t)c * NPIX] = 0.0f;
        return;
    }

    int ph = p / OUTS, pw = p - ph * OUTS;
    const float* f; int H;
    if      (li == 0) { f = f2; H = 200; }
    else if (li == 1) { f = f3; H = 100; }
    else if (li == 2) { f = f4; H = 50;  }
    else              { f = f5; H = 25;  }
    int W = H;
    int HW = H * W;
    int b = (n >= NR) ? 1 : 0;
    const float* base = f + ((size_t)b * CH + c0) * (size_t)HW;

    float x1 = g_meta[n * 4 + 0], y1 = g_meta[n * 4 + 1];
    float bw = g_meta[n * 4 + 2], bh = g_meta[n * 4 + 3];

    int yo0[2], yo1[2]; float lys[2]; float vyf[2];
    int xo0[2], xo1[2]; float lxs[2]; float vxf[2];
    #pragma unroll
    for (int i = 0; i < 2; i++) {
        float y = y1 + ((float)ph + 0.25f + 0.5f * (float)i) * bh;
        vyf[i] = ((y > -1.0f) && (y < (float)H)) ? 1.0f : 0.0f;
        float yc = fminf(fmaxf(y, 0.0f), (float)(H - 1));
        float y0f = floorf(yc);
        int y0 = (int)y0f;
        yo0[i] = y0 * W;
        yo1[i] = min(y0 + 1, H - 1) * W;
        lys[i] = yc - y0f;

        float x = x1 + ((float)pw + 0.25f + 0.5f * (float)i) * bw;
        vxf[i] = ((x > -1.0f) && (x < (float)W)) ? 1.0f : 0.0f;
        float xc = fminf(fmaxf(x, 0.0f), (float)(W - 1));
        float x0f = floorf(xc);
        xo0[i] = (int)x0f;
        xo1[i] = min((int)x0f + 1, W - 1);
        lxs[i] = xc - x0f;
    }

    int   off[16];
    float wgt[16];
    #pragma unroll
    for (int iy = 0; iy < 2; iy++) {
        #pragma unroll
        for (int ix = 0; ix < 2; ix++) {
            float v = vyf[iy] * vxf[ix];
            float ly = lys[iy], lx = lxs[ix];
            int s = (iy * 2 + ix) * 4;
            off[s + 0] = yo0[iy] + xo0[ix]; wgt[s + 0] = v * (1.0f - ly) * (1.0f - lx);
            off[s + 1] = yo0[iy] + xo1[ix]; wgt[s + 1] = v * (1.0f - ly) * lx;
            off[s + 2] = yo1[iy] + xo0[ix]; wgt[s + 2] = v * ly * (1.0f - lx);
            off[s + 3] = yo1[iy] + xo1[ix]; wgt[s + 3] = v * ly * lx;
        }
    }

    #pragma unroll
    for (int c = 0; c < 8; c++) {
        const float* bc = base + (size_t)c * HW;
        float v[16];
        #pragma unroll
        for (int q = 0; q < 16; q++) v[q] = bc[off[q]];
        float acc = 0.0f;
        #pragma unroll
        for (int q = 0; q < 16; q++) acc = fmaf(wgt[q], v[q], acc);
        g_X[obase + (size_t)c * NPIX] = tf32_rna(acc * 0.25f);
    }
}

// ---------------- heads weight concat: [Wc;Wr] -> g_WH (raw copy) -----------
#define N4WH (NHEAD * DDIM / 4)
__global__ void concat_wh_kernel(const float4* __restrict__ wc,
                                 const float4* __restrict__ wr) {
    int i = blockIdx.x * blockDim.x + threadIdx.x;
    if (i >= N4WH) return;
    int row = (i * 4) / DDIM;
    float4 v = (row < NCLS) ? wc[i] : wr[i - NCLS * DDIM / 4];
    ((float4*)g_WH)[i] = v;   // rows 401..511 stay zero (static init)
}

// ---------------- mma.sync tf32 GEMM, tile 128x128, ldmatrix frags ----------
// B-fragments rounded to tf32 (rna) in-register (W is raw fp32; A pre-rounded).
// P[z][M, (ld=DDIM)] = A[M,Kz]*round(B[N,Kz])^T ; BK=16, 5-stage cp.async,
// 2 CTAs/SM, 8 warps (4M x 2N), warp tile 32x64; LDSM.x4 fragment loads.
#define PADK   20
#define ASZ    (128 * PADK)
#define BSZ    (128 * PADK)
#define NSTG   5
#define GSMEM  ((NSTG * (ASZ + BSZ)) * 4)   // 102400 bytes

__global__ void __launch_bounds__(256, 2)
gemm_mma_tf32(const float* __restrict__ A, const float* __restrict__ B,
              float* __restrict__ P, int K, int kc) {
    extern __shared__ float sm[];
    float* smA = sm;
    float* smB = sm + NSTG * ASZ;
    uint32_t sA = smem_u32(smA);
    uint32_t sB = smem_u32(smB);

    const int tid = threadIdx.x;
    const int wid = tid >> 5, lane = tid & 31;
    const int grp = lane >> 2, tig = lane & 3;
    const int wm = (wid & 3) * 32;       // warp M offset
    const int wn = (wid >> 2) * 64;      // warp N offset

    const int rowA0 = blockIdx.y * 128;
    const int colB0 = blockIdx.x * 128;
    const int kbase = blockIdx.z * kc * 16;
    const int nk = kc;

    // ldmatrix lane->address mapping (byte offsets within a stage)
    // A atom ma: matrix m = lane>>3; row = wm+ma*16+(m&1)*8+(lane&7); kplus=(m>>1)*4
    // B group j (na=2j,2j+1): matrix m: na=2j+(m>>1); kplus=(m&1)*4
    const int mrow = lane & 7;
    uint32_t aoff[2], boff[4];
    {
        int aside = (lane >> 3) & 1, ahalf = (lane >> 4) & 1;
        #pragma unroll
        for (int ma = 0; ma < 2; ma++)
            aoff[ma] = (uint32_t)(((wm + ma * 16 + aside * 8 + mrow) * PADK + ahalf * 4) * 4);
        int bna = (lane >> 4) & 1, bkh = (lane >> 3) & 1;
        #pragma unroll
        for (int j = 0; j < 4; j++)
            boff[j] = (uint32_t)(((wn + (2 * j + bna) * 8 + mrow) * PADK + bkh * 4) * 4);
    }

    // global->smem mapping: 2 CP16 per thread for A, 2 for B (16 floats/row)
    const int grow = tid >> 1, gc = (tid & 1) * 8;
    const float* gA = A + (size_t)(rowA0 + grow) * K + kbase + gc;
    const float* gB = B + (size_t)(colB0 + grow) * K + kbase + gc;
    const uint32_t dA0 = sA + (uint32_t)(grow * PADK + gc) * 4;
    const uint32_t dA1 = dA0 + 16;
    const uint32_t dB0 = sB + (uint32_t)(grow * PADK + gc) * 4;
    const uint32_t dB1 = dB0 + 16;

    float c[2][8][4];
    #pragma unroll
    for (int i = 0; i < 2; i++)
        #pragma unroll
        for (int j = 0; j < 8; j++)
            #pragma unroll
            for (int q = 0; q < 4; q++) c[i][j][q] = 0.0f;

    #pragma unroll
    for (int s = 0; s < NSTG - 1; s++) {
        if (s < nk) {
            CP16(dA0 + (uint32_t)(s * ASZ * 4), gA + (size_t)s * 16);
            CP16(dA1 + (uint32_t)(s * ASZ * 4), gA + (size_t)s * 16 + 4);
            CP16(dB0 + (uint32_t)(s * BSZ * 4), gB + (size_t)s * 16);
            CP16(dB1 + (uint32_t)(s * BSZ * 4), gB + (size_t)s * 16 + 4);
        }
        CPCOMMIT();
    }

    int stage = 0;
    for (int kt = 0; kt < nk; kt++) {
        CPWAIT3();            // chunks 0..kt complete
        __syncthreads();      // readers of stage being overwritten are done

        int pk = kt + NSTG - 1;
        int ps = stage + (NSTG - 1); if (ps >= NSTG) ps -= NSTG;
        if (pk < nk) {
            CP16(dA0 + (uint32_t)(ps * ASZ * 4), gA + (size_t)pk * 16);
            CP16(dA1 + (uint32_t)(ps * ASZ * 4), gA + (size_t)pk * 16 + 4);
            CP16(dB0 + (uint32_t)(ps * BSZ * 4), gB + (size_t)pk * 16);
            CP16(dB1 + (uint32_t)(ps * BSZ * 4), gB + (size_t)pk * 16 + 4);
        }
        CPCOMMIT();

        const uint32_t abase = sA + (uint32_t)(stage * ASZ * 4);
        const uint32_t bbase = sB + (uint32_t)(stage * BSZ * 4);

        #pragma unroll
        for (int ka = 0; ka < 2; ka++) {
            const uint32_t kb = (uint32_t)(ka * 8 * 4);
            uint32_t a[2][4], b[8][2];
            LDSM4(a[0][0], a[0][1], a[0][2], a[0][3], abase + aoff[0] + kb);
            LDSM4(a[1][0], a[1][1], a[1][2], a[1][3], abase + aoff[1] + kb);
            #pragma unroll
            for (int j = 0; j < 4; j++) {
                uint32_t t0, t1, t2, t3;
                LDSM4(t0, t1, t2, t3, bbase + boff[j] + kb);
                b[2 * j][0]     = tf32_rna_u(t0);
                b[2 * j][1]     = tf32_rna_u(t1);
                b[2 * j + 1][0] = tf32_rna_u(t2);
                b[2 * j + 1][1] = tf32_rna_u(t3);
            }
            #pragma unroll
            for (int ma = 0; ma < 2; ma++)
                #pragma unroll
                for (int na = 0; na < 8; na++)
                    mma_tf32(c[ma][na], a[ma], b[na]);
        }

        if (++stage == NSTG) stage = 0;
    }

    float* Pp = P + (size_t)blockIdx.z * NROI * DDIM;
    #pragma unroll
    for (int ma = 0; ma < 2; ma++) {
        int r0 = rowA0 + wm + ma * 16 + grp;
        #pragma unroll
        for (int na = 0; na < 8; na++) {
            int col = colB0 + wn + na * 8 + tig * 2;
            *(float2*)&Pp[(size_t)r0 * DDIM + col]       = make_float2(c[ma][na][0], c[ma][na][1]);
            *(float2*)&Pp[(size_t)(r0 + 8) * DDIM + col] = make_float2(c[ma][na][2], c[ma][na][3]);
        }
    }
}

// ---------------- split-K reduce + bias + relu (+ tf32 round) ----------------
template<int NP, int RND>
__global__ void __launch_bounds__(256)
reduce_kernel(const float* __restrict__ bias, float* __restrict__ C) {
    int i = blockIdx.x * blockDim.x + threadIdx.x;   // float4 index
    if (i >= NROI * DDIM / 4) return;
    const float4* P = (const float4*)g_P;
    const size_t stride = (size_t)NROI * DDIM / 4;
    float4 v = P[i];
    #pragma unroll
    for (int p = 1; p < NP; p++) {
        float4 u = P[i + p * stride];
        v.x += u.x; v.y += u.y; v.z += u.z; v.w += u.w;
    }
    int col = (i * 4) & (DDIM - 1);
    float4 bv = *(const float4*)&bias[col];
    float4 r;
    r.x = fmaxf(v.x + bv.x, 0.0f);
    r.y = fmaxf(v.y + bv.y, 0.0f);
    r.z = fmaxf(v.z + bv.z, 0.0f);
    r.w = fmaxf(v.w + bv.w, 0.0f);
    if (RND) { r.x = tf32_rna(r.x); r.y = tf32_rna(r.y);
               r.z = tf32_rna(r.z); r.w = tf32_rna(r.w); }
    ((float4*)C)[i] = r;
}

// ---------------- heads reduce: bias + scatter into cls/reg layout ----------
__global__ void __launch_bounds__(256)
reduce_heads_kernel(const float* __restrict__ bc, const float* __restrict__ br,
                    float* __restrict__ out) {
    int i = blockIdx.x * blockDim.x + threadIdx.x;
    if (i >= NROI * NHEAD) return;
    int m = i / NHEAD;
    int col = i - m * NHEAD;
    const float* P = g_P;
    const size_t stride = (size_t)NROI * DDIM;
    size_t o = (size_t)m * DDIM + col;
    float v = P[o];
    #pragma unroll
    for (int p = 1; p < KSH; p++) v += P[o + p * stride];
    if (col < NCLS)
        out[(size_t)m * NCLS + col] = v + bc[col];
    else
        out[(size_t)NROI * NCLS + (size_t)m * NREG + (col - NCLS)] = v + br[col - NCLS];
}

// ---------------- launch ----------------
extern "C" void kernel_launch(void* const* d_in, const int* in_sizes, int n_in,
                              void* d_out, int out_size) {
    const float* f2   = (const float*)d_in[0];
    const float* f3   = (const float*)d_in[1];
    const float* f4   = (const float*)d_in[2];
    const float* f5   = (const float*)d_in[3];
    const float* rois = (const float*)d_in[4];
    const float* W1   = (const float*)d_in[5];
    const float* b1   = (const float*)d_in[6];
    const float* W2   = (const float*)d_in[7];
    const float* b2   = (const float*)d_in[8];
    const float* Wc   = (const float*)d_in[9];
    const float* bc   = (const float*)d_in[10];
    const float* Wr   = (const float*)d_in[11];
    const float* br   = (const float*)d_in[12];
    float* out = (float*)d_out;

    float *X, *Y, *Z, *WH, *Pb;
    cudaGetSymbolAddress((void**)&X, g_X);
    cudaGetSymbolAddress((void**)&Y, g_Y);
    cudaGetSymbolAddress((void**)&Z, g_Z);
    cudaGetSymbolAddress((void**)&WH, g_WH);
    cudaGetSymbolAddress((void**)&Pb, g_P);

    cudaFuncSetAttribute(gemm_mma_tf32, cudaFuncAttributeMaxDynamicSharedMemorySize, GSMEM);

    roi_prep_kernel<<<(NROI + 255) / 256, 256>>>(rois);

    int total = NROI * (CH / 8) * NPIX;
    roi_align_kernel<<<(total + 255) / 256, 256>>>(f2, f3, f4, f5);

    concat_wh_kernel<<<(N4WH + 255) / 256, 256>>>((const float4*)Wc, (const float4*)Wr);

    int nred = NROI * DDIM / 4;
    // fc1: K=12544, 784 BK-iters, 196 per split (grid 8x8x4 = 256 CTAs, 1 wave)
    gemm_mma_tf32<<<dim3(DDIM / 128, NROI / 128, KS1), 256, GSMEM>>>(X, W1, Pb, FDIM, 196);
    reduce_kernel<KS1, 1><<<(nred + 255) / 256, 256>>>(b1, Y);
    // fc2: K=1024, 64 BK-iters, 16 per split (grid 8x8x4)
    gemm_mma_tf32<<<dim3(DDIM / 128, NROI / 128, KS2), 256, GSMEM>>>(Y, W2, Pb, DDIM, 16);
    reduce_kernel<KS2, 1><<<(nred + 255) / 256, 256>>>(b2, Z);
    // heads: M=1024, N=512(pad), K=1024, 8 per split (grid 4x8x8 = 256 CTAs)
    gemm_mma_tf32<<<dim3(NHPAD / 128, NROI / 128, KSH), 256, GSMEM>>>(Z, WH, Pb, DDIM, 8);
    reduce_heads_kernel<<<(NROI * NHEAD + 255) / 256, 256>>>(bc, br, out);
}

// round 17
// speedup vs baseline: 1.1454x; 1.0043x over previous
#include <cuda_runtime.h>
#include <cstdint>
#include <math.h>

// ---------------- problem constants ----------------
#define NBS   2
#define NR    512
#define NROI  (NBS*NR)          // 1024
#define CH    256
#define OUTS  7
#define NPIX  (OUTS*OUTS)       // 49
#define FDIM  (CH*NPIX)         // 12544
#define DDIM  1024
#define NCLS  81
#define NREG  320
#define NHEAD (NCLS + NREG)     // 401
#define NHPAD 512               // padded head cols (4 x 128)
#define KS1   4                 // split-K for fc1
#define KS2   4                 // split-K for fc2
#define KSH   8                 // split-K for heads (grid 4x8x8 = 256 CTAs)

// ---------------- device scratch ----------------
__device__ float g_X[(size_t)NROI * FDIM];      // pooled features (tf32-rounded)
__device__ float g_Y[(size_t)NROI * DDIM];      // fc1 out (tf32-rounded)
__device__ float g_Z[(size_t)NROI * DDIM];      // fc2 out (tf32-rounded)
__device__ float g_W1r[(size_t)DDIM * FDIM];    // tf32 W1
__device__ float g_W2r[(size_t)DDIM * DDIM];    // tf32 W2
__device__ float g_WHr[(size_t)NHPAD * DDIM];   // tf32 [Wc;Wr;0-pad] (zero-init)
__device__ float g_P[(size_t)KSH * NROI * DDIM]; // split-K partials (32MB)
__device__ int   g_lvl[NROI];
__device__ float g_meta[NROI * 4];

// ---------------- helpers ----------------
__device__ __forceinline__ float tf32_rna(float x) {
    uint32_t r; asm("cvt.rna.tf32.f32 %0, %1;" : "=r"(r) : "f"(x));
    return __uint_as_float(r);
}
__device__ __forceinline__ uint32_t smem_u32(const void* p) {
    uint32_t a;
    asm("{ .reg .u64 t; cvta.to.shared.u64 t, %1; cvt.u32.u64 %0, t; }" : "=r"(a) : "l"(p));
    return a;
}
#define CP16(dst, src) \
    asm volatile("cp.async.cg.shared.global [%0], [%1], 16;" :: "r"(dst), "l"(src) : "memory")
#define CPCOMMIT() asm volatile("cp.async.commit_group;" ::: "memory")
#define CPWAIT3()  asm volatile("cp.async.wait_group 3;" ::: "memory")
#define LDSM4(r0, r1, r2, r3, addr) \
    asm volatile("ldmatrix.sync.aligned.m8n8.x4.shared.b16 {%0,%1,%2,%3}, [%4];" \
        : "=r"(r0), "=r"(r1), "=r"(r2), "=r"(r3) : "r"(addr))

__device__ __forceinline__ void mma_tf32(float c[4], const uint32_t a[4], const uint32_t b[2]) {
    asm volatile(
        "mma.sync.aligned.m16n8k8.row.col.f32.tf32.tf32.f32 "
        "{%0,%1,%2,%3}, {%4,%5,%6,%7}, {%8,%9}, {%0,%1,%2,%3};"
        : "+f"(c[0]), "+f"(c[1]), "+f"(c[2]), "+f"(c[3])
        : "r"(a[0]), "r"(a[1]), "r"(a[2]), "r"(a[3]), "r"(b[0]), "r"(b[1]));
}

// ---------------- roi prep ----------------
__global__ void roi_prep_kernel(const float* __restrict__ rois) {
    int i = blockIdx.x * blockDim.x + threadIdx.x;
    if (i >= NROI) return;
    float x1 = rois[i * 4 + 0], y1 = rois[i * 4 + 1];
    float x2 = rois[i * 4 + 2], y2 = rois[i * 4 + 3];
    float w = x2 - x1, h = y2 - y1;
    float lv = floorf(4.0f + log2f(sqrtf(w * h) / 224.0f + 1e-6f));
    int li = (int)lv - 2;
    g_lvl[i] = li;
    int lic = li < 0 ? 0 : (li > 3 ? 3 : li);
    float scale = 1.0f / (float)(4 << lic);
    float x1s = x1 * scale, y1s = y1 * scale;
    float rw = fmaxf(x2 * scale - x1s, 1.0f);
    float rh = fmaxf(y2 * scale - y1s, 1.0f);
    g_meta[i * 4 + 0] = x1s;
    g_meta[i * 4 + 1] = y1s;
    g_meta[i * 4 + 2] = rw / (float)OUTS;
    g_meta[i * 4 + 3] = rh / (float)OUTS;
}

// ---------------- roi align: 8 channels/thread, branch-free gathers ----------
__global__ void __launch_bounds__(256)
roi_align_kernel(const float* __restrict__ f2, const float* __restrict__ f3,
                 const float* __restrict__ f4, const float* __restrict__ f5) {
    int idx = blockIdx.x * blockDim.x + threadIdx.x;
    if (idx >= NROI * (CH / 8) * NPIX) return;
    int n   = idx / ((CH / 8) * NPIX);
    int rem = idx - n * ((CH / 8) * NPIX);
    int c8  = rem / NPIX;
    int p   = rem - c8 * NPIX;
    int c0  = c8 * 8;

    size_t obase = (size_t)n * FDIM + (size_t)c0 * NPIX + p;

    int li = g_lvl[n];
    if (li < 0 || li > 3) {
        #pragma unroll
        for (int c = 0; c < 8; c++) g_X[obase + (size_t)c * NPIX] = 0.0f;
        return;
    }

    int ph = p / OUTS, pw = p - ph * OUTS;
    const float* f; int H;
    if      (li == 0) { f = f2; H = 200; }
    else if (li == 1) { f = f3; H = 100; }
    else if (li == 2) { f = f4; H = 50;  }
    else              { f = f5; H = 25;  }
    int W = H;
    int HW = H * W;
    int b = (n >= NR) ? 1 : 0;
    const float* base = f + ((size_t)b * CH + c0) * (size_t)HW;

    float x1 = g_meta[n * 4 + 0], y1 = g_meta[n * 4 + 1];
    float bw = g_meta[n * 4 + 2], bh = g_meta[n * 4 + 3];

    int yo0[2], yo1[2]; float lys[2]; float vyf[2];
    int xo0[2], xo1[2]; float lxs[2]; float vxf[2];
    #pragma unroll
    for (int i = 0; i < 2; i++) {
        float y = y1 + ((float)ph + 0.25f + 0.5f * (float)i) * bh;
        vyf[i] = ((y > -1.0f) && (y < (float)H)) ? 1.0f : 0.0f;
        float yc = fminf(fmaxf(y, 0.0f), (float)(H - 1));
        float y0f = floorf(yc);
        int y0 = (int)y0f;
        yo0[i] = y0 * W;
        yo1[i] = min(y0 + 1, H - 1) * W;
        lys[i] = yc - y0f;

        float x = x1 + ((float)pw + 0.25f + 0.5f * (float)i) * bw;
        vxf[i] = ((x > -1.0f) && (x < (float)W)) ? 1.0f : 0.0f;
        float xc = fminf(fmaxf(x, 0.0f), (float)(W - 1));
        float x0f = floorf(xc);
        xo0[i] = (int)x0f;
        xo1[i] = min((int)x0f + 1, W - 1);
        lxs[i] = xc - x0f;
    }

    int   off[16];
    float wgt[16];
    #pragma unroll
    for (int iy = 0; iy < 2; iy++) {
        #pragma unroll
        for (int ix = 0; ix < 2; ix++) {
            float v = vyf[iy] * vxf[ix];
            float ly = lys[iy], lx = lxs[ix];
            int s = (iy * 2 + ix) * 4;
            off[s + 0] = yo0[iy] + xo0[ix]; wgt[s + 0] = v * (1.0f - ly) * (1.0f - lx);
            off[s + 1] = yo0[iy] + xo1[ix]; wgt[s + 1] = v * (1.0f - ly) * lx;
            off[s + 2] = yo1[iy] + xo0[ix]; wgt[s + 2] = v * ly * (1.0f - lx);
            off[s + 3] = yo1[iy] + xo1[ix]; wgt[s + 3] = v * ly * lx;
        }
    }

    #pragma unroll
    for (int c = 0; c < 8; c++) {
        const float* bc = base + (size_t)c * HW;
        float v[16];
        #pragma unroll
        for (int q = 0; q < 16; q++) v[q] = bc[off[q]];
        float acc = 0.0f;
        #pragma unroll
        for (int q = 0; q < 16; q++) acc = fmaf(wgt[q], v[q], acc);
        g_X[obase + (size_t)c * NPIX] = tf32_rna(acc * 0.25f);
    }
}

// ---------------- tf32 round: W1, W2, and concat(Wc,Wr) -> g_WHr ------------
#define N4W1 (DDIM * FDIM / 4)
#define N4W2 (DDIM * DDIM / 4)
#define N4WH (NHEAD * DDIM / 4)
__global__ void round_all_kernel(const float4* __restrict__ w1,
                                 const float4* __restrict__ w2,
                                 const float4* __restrict__ wc,
                                 const float4* __restrict__ wr) {
    int i = blockIdx.x * blockDim.x + threadIdx.x;
    const float4* in; int j;
    if (i < N4W1) { in = w1; j = i; }
    else if (i < N4W1 + N4W2) { in = w2; j = i - N4W1; }
    else if (i < N4W1 + N4W2 + N4WH) {
        j = i - N4W1 - N4W2;
        int row = (j * 4) / DDIM;
        if (row < NCLS) { in = wc; }
        else            { in = wr; j -= NCLS * DDIM / 4; }
    } else return;
    float4 v = in[j];
    v.x = tf32_rna(v.x); v.y = tf32_rna(v.y);
    v.z = tf32_rna(v.z); v.w = tf32_rna(v.w);
    if (i < N4W1)              ((float4*)g_W1r)[i] = v;
    else if (i < N4W1 + N4W2)  ((float4*)g_W2r)[i - N4W1] = v;
    else                       ((float4*)g_WHr)[i - N4W1 - N4W2] = v; // rows 401..511 stay 0
}

// ---------------- mma.sync tf32 GEMM, tile 128x128, ldmatrix frags ----------
// Operands pre-rounded to tf32 (X/Y/Z by producers, W by round_all) — no cvt
// in the mainloop. P[z][M, ld=DDIM] = A[M,Kz]*B[N,Kz]^T ; BK=16, 5-stage
// cp.async, 2 CTAs/SM, 8 warps (4M x 2N), warp tile 32x64; LDSM.x4 frags.
#define PADK   20
#define ASZ    (128 * PADK)
#define BSZ    (128 * PADK)
#define NSTG   5
#define GSMEM  ((NSTG * (ASZ + BSZ)) * 4)   // 102400 bytes

__global__ void __launch_bounds__(256, 2)
gemm_mma_tf32(const float* __restrict__ A, const float* __restrict__ B,
              float* __restrict__ P, int K, int kc) {
    extern __shared__ float sm[];
    float* smA = sm;
    float* smB = sm + NSTG * ASZ;
    uint32_t sA = smem_u32(smA);
    uint32_t sB = smem_u32(smB);

    const int tid = threadIdx.x;
    const int wid = tid >> 5, lane = tid & 31;
    const int grp = lane >> 2, tig = lane & 3;
    const int wm = (wid & 3) * 32;       // warp M offset
    const int wn = (wid >> 2) * 64;      // warp N offset

    const int rowA0 = blockIdx.y * 128;
    const int colB0 = blockIdx.x * 128;
    const int kbase = blockIdx.z * kc * 16;
    const int nk = kc;

    // ldmatrix lane->address mapping (byte offsets within a stage)
    const int mrow = lane & 7;
    uint32_t aoff[2], boff[4];
    {
        int aside = (lane >> 3) & 1, ahalf = (lane >> 4) & 1;
        #pragma unroll
        for (int ma = 0; ma < 2; ma++)
            aoff[ma] = (uint32_t)(((wm + ma * 16 + aside * 8 + mrow) * PADK + ahalf * 4) * 4);
        int bna = (lane >> 4) & 1, bkh = (lane >> 3) & 1;
        #pragma unroll
        for (int j = 0; j < 4; j++)
            boff[j] = (uint32_t)(((wn + (2 * j + bna) * 8 + mrow) * PADK + bkh * 4) * 4);
    }

    const int grow = tid >> 1, gc = (tid & 1) * 8;
    const float* gA = A + (size_t)(rowA0 + grow) * K + kbase + gc;
    const float* gB = B + (size_t)(colB0 + grow) * K + kbase + gc;
    const uint32_t dA0 = sA + (uint32_t)(grow * PADK + gc) * 4;
    const uint32_t dA1 = dA0 + 16;
    const uint32_t dB0 = sB + (uint32_t)(grow * PADK + gc) * 4;
    const uint32_t dB1 = dB0 + 16;

    float c[2][8][4];
    #pragma unroll
    for (int i = 0; i < 2; i++)
        #pragma unroll
        for (int j = 0; j < 8; j++)
            #pragma unroll
            for (int q = 0; q < 4; q++) c[i][j][q] = 0.0f;

    #pragma unroll
    for (int s = 0; s < NSTG - 1; s++) {
        if (s < nk) {
            CP16(dA0 + (uint32_t)(s * ASZ * 4), gA + (size_t)s * 16);
            CP16(dA1 + (uint32_t)(s * ASZ * 4), gA + (size_t)s * 16 + 4);
            CP16(dB0 + (uint32_t)(s * BSZ * 4), gB + (size_t)s * 16);
            CP16(dB1 + (uint32_t)(s * BSZ * 4), gB + (size_t)s * 16 + 4);
        }
        CPCOMMIT();
    }

    int stage = 0;
    for (int kt = 0; kt < nk; kt++) {
        CPWAIT3();            // chunks 0..kt complete
        __syncthreads();      // readers of stage being overwritten are done

        int pk = kt + NSTG - 1;
        int ps = stage + (NSTG - 1); if (ps >= NSTG) ps -= NSTG;
        if (pk < nk) {
            CP16(dA0 + (uint32_t)(ps * ASZ * 4), gA + (size_t)pk * 16);
            CP16(dA1 + (uint32_t)(ps * ASZ * 4), gA + (size_t)pk * 16 + 4);
            CP16(dB0 + (uint32_t)(ps * BSZ * 4), gB + (size_t)pk * 16);
            CP16(dB1 + (uint32_t)(ps * BSZ * 4), gB + (size_t)pk * 16 + 4);
        }
        CPCOMMIT();

        const uint32_t abase = sA + (uint32_t)(stage * ASZ * 4);
        const uint32_t bbase = sB + (uint32_t)(stage * BSZ * 4);

        #pragma unroll
        for (int ka = 0; ka < 2; ka++) {
            const uint32_t kb = (uint32_t)(ka * 8 * 4);
            uint32_t a[2][4], b[8][2];
            LDSM4(a[0][0], a[0][1], a[0][2], a[0][3], abase + aoff[0] + kb);
            LDSM4(a[1][0], a[1][1], a[1][2], a[1][3], abase + aoff[1] + kb);
            #pragma unroll
            for (int j = 0; j < 4; j++) {
                LDSM4(b[2 * j][0], b[2 * j][1], b[2 * j + 1][0], b[2 * j + 1][1],
                      bbase + boff[j] + kb);
            }
            #pragma unroll
            for (int ma = 0; ma < 2; ma++)
                #pragma unroll
                for (int na = 0; na < 8; na++)
                    mma_tf32(c[ma][na], a[ma], b[na]);
        }

        if (++stage == NSTG) stage = 0;
    }

    float* Pp = P + (size_t)blockIdx.z * NROI * DDIM;
    #pragma unroll
    for (int ma = 0; ma < 2; ma++) {
        int r0 = rowA0 + wm + ma * 16 + grp;
        #pragma unroll
        for (int na = 0; na < 8; na++) {
            int col = colB0 + wn + na * 8 + tig * 2;
            *(float2*)&Pp[(size_t)r0 * DDIM + col]       = make_float2(c[ma][na][0], c[ma][na][1]);
            *(float2*)&Pp[(size_t)(r0 + 8) * DDIM + col] = make_float2(c[ma][na][2], c[ma][na][3]);
        }
    }
}

// ---------------- split-K reduce + bias + relu (+ tf32 round) ----------------
template<int NP, int RND>
__global__ void __launch_bounds__(256)
reduce_kernel(const float* __restrict__ bias, float* __restrict__ C) {
    int i = blockIdx.x * blockDim.x + threadIdx.x;   // float4 index
    if (i >= NROI * DDIM / 4) return;
    const float4* P = (const float4*)g_P;
    const size_t stride = (size_t)NROI * DDIM / 4;
    float4 v = P[i];
    #pragma unroll
    for (int p = 1; p < NP; p++) {
        float4 u = P[i + p * stride];
        v.x += u.x; v.y += u.y; v.z += u.z; v.w += u.w;
    }
    int col = (i * 4) & (DDIM - 1);
    float4 bv = *(const float4*)&bias[col];
    float4 r;
    r.x = fmaxf(v.x + bv.x, 0.0f);
    r.y = fmaxf(v.y + bv.y, 0.0f);
    r.z = fmaxf(v.z + bv.z, 0.0f);
    r.w = fmaxf(v.w + bv.w, 0.0f);
    if (RND) { r.x = tf32_rna(r.x); r.y = tf32_rna(r.y);
               r.z = tf32_rna(r.z); r.w = tf32_rna(r.w); }
    ((float4*)C)[i] = r;
}

// ---------------- heads reduce: bias + scatter into cls/reg layout ----------
__global__ void __launch_bounds__(256)
reduce_heads_kernel(const float* __restrict__ bc, const float* __restrict__ br,
                    float* __restrict__ out) {
    int i = blockIdx.x * blockDim.x + threadIdx.x;
    if (i >= NROI * NHEAD) return;
    int m = i / NHEAD;
    int col = i - m * NHEAD;
    const float* P = g_P;
    const size_t stride = (size_t)NROI * DDIM;
    size_t o = (size_t)m * DDIM + col;
    float v = P[o];
    #pragma unroll
    for (int p = 1; p < KSH; p++) v += P[o + p * stride];
    if (col < NCLS)
        out[(size_t)m * NCLS + col] = v + bc[col];
    else
        out[(size_t)NROI * NCLS + (size_t)m * NREG + (col - NCLS)] = v + br[col - NCLS];
}

// ---------------- launch ----------------
extern "C" void kernel_launch(void* const* d_in, const int* in_sizes, int n_in,
                              void* d_out, int out_size) {
    const float* f2   = (const float*)d_in[0];
    const float* f3   = (const float*)d_in[1];
    const float* f4   = (const float*)d_in[2];
    const float* f5   = (const float*)d_in[3];
    const float* rois = (const float*)d_in[4];
    const float* W1   = (const float*)d_in[5];
    const float* b1   = (const float*)d_in[6];
    const float* W2   = (const float*)d_in[7];
    const float* b2   = (const float*)d_in[8];
    const float* Wc   = (const float*)d_in[9];
    const float* bc   = (const float*)d_in[10];
    const float* Wr   = (const float*)d_in[11];
    const float* br   = (const float*)d_in[12];
    float* out = (float*)d_out;

    float *X, *Y, *Z, *W1r, *W2r, *WHr, *Pb;
    cudaGetSymbolAddress((void**)&X, g_X);
    cudaGetSymbolAddress((void**)&Y, g_Y);
    cudaGetSymbolAddress((void**)&Z, g_Z);
    cudaGetSymbolAddress((void**)&W1r, g_W1r);
    cudaGetSymbolAddress((void**)&W2r, g_W2r);
    cudaGetSymbolAddress((void**)&WHr, g_WHr);
    cudaGetSymbolAddress((void**)&Pb, g_P);

    cudaFuncSetAttribute(gemm_mma_tf32, cudaFuncAttributeMaxDynamicSharedMemorySize, GSMEM);

    roi_prep_kernel<<<(NROI + 255) / 256, 256>>>(rois);

    int total = NROI * (CH / 8) * NPIX;
    roi_align_kernel<<<(total + 255) / 256, 256>>>(f2, f3, f4, f5);

    round_all_kernel<<<(N4W1 + N4W2 + N4WH + 255) / 256, 256>>>(
        (const float4*)W1, (const float4*)W2, (const float4*)Wc, (const float4*)Wr);

    int nred = NROI * DDIM / 4;
    // fc1: K=12544, 784 BK-iters, 196 per split (grid 8x8x4 = 256 CTAs, 1 wave)
    gemm_mma_tf32<<<dim3(DDIM / 128, NROI / 128, KS1), 256, GSMEM>>>(X, W1r, Pb, FDIM, 196);
    reduce_kernel<KS1, 1><<<(nred + 255) / 256, 256>>>(b1, Y);
    // fc2: K=1024, 64 BK-iters, 16 per split (grid 8x8x4)
    gemm_mma_tf32<<<dim3(DDIM / 128, NROI / 128, KS2), 256, GSMEM>>>(Y, W2r, Pb, DDIM, 16);
    reduce_kernel<KS2, 1><<<(nred + 255) / 256, 256>>>(b2, Z);
    // heads: M=1024, N=512(pad), K=1024, 8 per split (grid 4x8x8 = 256 CTAs)
    gemm_mma_tf32<<<dim3(NHPAD / 128, NROI / 128, KSH), 256, GSMEM>>>(Z, WHr, Pb, DDIM, 8);
    reduce_heads_kernel<<<(NROI * NHEAD + 255) / 256, 256>>>(bc, br, out);
}